// round 13
// baseline (speedup 1.0000x reference)
#include <cuda_runtime.h>
#include <cuda_bf16.h>
#include <math.h>
#include <stdint.h>

// ================= problem constants =================
#define IMG    256
#define CCH    192
#define NHEADS 6
#define DTOT   576
#define TOK    64
#define NWIN   4096
#define NTOK   262144

// ================= device scratch =================
__device__ float g_ao [(size_t)NTOK * CCH];             // 201 MB
__device__ uint32_t g_wq2[6 * 2 * 12 * 12 * 64];        // qkv frags [head][half][nt12][s12][64]
__device__ uint32_t g_wp_frag[24 * 24 * 64];            // proj frags [nt24][step24][64]
__device__ float g_bq[DTOT];
__device__ float g_rb[NHEADS * TOK * TOK];

// ================= asm helpers (baseline sm_103 PTX only) =================
__device__ __forceinline__ uint32_t smem_u32(const void* p) {
    uint32_t a;
    asm("{ .reg .u64 t; cvta.to.shared.u64 t, %1; cvt.u32.u64 %0, t; }" : "=r"(a) : "l"(p));
    return a;
}
__device__ __forceinline__ void ldsm4(uint32_t* r, uint32_t addr) {
    asm volatile("ldmatrix.sync.aligned.m8n8.x4.shared.b16 {%0,%1,%2,%3}, [%4];"
                 : "=r"(r[0]), "=r"(r[1]), "=r"(r[2]), "=r"(r[3]) : "r"(addr));
}
__device__ __forceinline__ void lds64(uint32_t* r, uint32_t addr) {
    asm volatile("ld.shared.v2.u32 {%0,%1}, [%2];" : "=r"(r[0]), "=r"(r[1]) : "r"(addr));
}
__device__ __forceinline__ void mma16816(float* d, const uint32_t* a, const uint32_t* b) {
    asm volatile("mma.sync.aligned.m16n8k16.row.col.f32.bf16.bf16.f32 "
                 "{%0,%1,%2,%3}, {%4,%5,%6,%7}, {%8,%9}, {%0,%1,%2,%3};"
                 : "+f"(d[0]), "+f"(d[1]), "+f"(d[2]), "+f"(d[3])
                 : "r"(a[0]), "r"(a[1]), "r"(a[2]), "r"(a[3]), "r"(b[0]), "r"(b[1]));
}
#define BAR_ARRIVE(id) asm volatile("bar.arrive %0, 256;" :: "r"(id) : "memory")
#define BAR_SYNC(id)   asm volatile("bar.sync %0, 256;"   :: "r"(id) : "memory")
#define BAR_G128(id)   asm volatile("bar.sync %0, 128;"   :: "r"(id) : "memory")

__device__ __forceinline__ uint16_t bf_hi(float v) {
    return __bfloat16_as_ushort(__float2bfloat16(v));
}
__device__ __forceinline__ uint16_t bf_lo(float v) {
    __nv_bfloat16 h = __float2bfloat16(v);
    return __bfloat16_as_ushort(__float2bfloat16(v - __bfloat162float(h)));
}
__device__ __forceinline__ uint32_t pk(uint16_t a, uint16_t b) {
    return (uint32_t)a | ((uint32_t)b << 16);
}

// ================= kernel: weight prep =================
__global__ void prep_kernel(const float* __restrict__ qkv_w, const float* __restrict__ proj_w,
                            const float* __restrict__ q_bias, const float* __restrict__ v_bias) {
    int gtid = blockIdx.x * blockDim.x + threadIdx.x;
    int nth = gridDim.x * blockDim.x;
    for (int idx = gtid; idx < 6 * 2 * 12 * 12 * 64; idx += nth) {
        int r = idx & 1, l = (idx >> 1) & 31;
        int blk = idx >> 6;
        int s = blk % 12; blk /= 12;
        int nt = blk % 12; blk /= 12;
        int hf = blk & 1, hd = blk >> 1;
        int k = hf * 96 + (s % 6) * 16 + 2 * (l & 3) + 8 * r;
        int n = hd * 96 + nt * 8 + (l >> 2);
        float v0 = qkv_w[k * DTOT + n];
        float v1 = qkv_w[(k + 1) * DTOT + n];
        uint32_t p0 = (s < 6) ? bf_hi(v0) : bf_lo(v0);
        uint32_t p1 = (s < 6) ? bf_hi(v1) : bf_lo(v1);
        g_wq2[idx] = p0 | (p1 << 16);
    }
    for (int idx = gtid; idx < 24 * 24 * 64; idx += nth) {
        int r = idx & 1, l = (idx >> 1) & 31;
        int st = (idx >> 6) % 24, nt = (idx >> 6) / 24;
        int ko = 16 * (st % 12) + 2 * (l & 3) + 8 * r;
        int n = nt * 8 + (l >> 2);
        float v0 = proj_w[ko * CCH + n];
        float v1 = proj_w[(ko + 1) * CCH + n];
        uint32_t p0 = (st < 12) ? bf_hi(v0) : bf_lo(v0);
        uint32_t p1 = (st < 12) ? bf_hi(v1) : bf_lo(v1);
        g_wp_frag[idx] = p0 | (p1 << 16);
    }
    for (int n = gtid; n < DTOT; n += nth)
        g_bq[n] = (n < 192) ? q_bias[n] : ((n < 384) ? 0.0f : v_bias[n - 384]);
}

// ================= kernel: CPB MLP + gather =================
__global__ void cpb_kernel(const float* __restrict__ w1, const float* __restrict__ b1,
                           const float* __restrict__ w2) {
    __shared__ float tab16[225][6];
    int t = threadIdx.x;
    if (t < 225) {
        float ci = (float)(t / 15 - 7) * (8.0f / 7.0f);
        float cj = (float)(t % 15 - 7) * (8.0f / 7.0f);
        const float inv_log8 = 1.0f / logf(8.0f);
        float tx = copysignf(log1pf(fabsf(ci)) * inv_log8, ci);
        float ty = copysignf(log1pf(fabsf(cj)) * inv_log8, cj);
        float o[6] = {0.f, 0.f, 0.f, 0.f, 0.f, 0.f};
        for (int k = 0; k < 512; k++) {
            float h = fmaxf(tx * w1[k] + ty * w1[512 + k] + b1[k], 0.0f);
            #pragma unroll
            for (int hh = 0; hh < 6; hh++) o[hh] += h * w2[k * 6 + hh];
        }
        #pragma unroll
        for (int hh = 0; hh < 6; hh++) tab16[t][hh] = 16.0f / (1.0f + expf(-o[hh]));
    }
    __syncthreads();
    for (int idx = t; idx < NHEADS * TOK * TOK; idx += blockDim.x) {
        int h = idx >> 12;
        int r = idx & 4095;
        int p = r >> 6, q = r & 63;
        int ri = (p >> 3) - (q >> 3) + 7;
        int rj = (p & 7) - (q & 7) + 7;
        g_rb[idx] = tab16[ri * 15 + rj][h];
    }
}

// ================= fused kernel: column-warp GEMM + specialized attention (round-12 proven) =================
#define A_ROW_B  784
#define OFF_A    0
#define OFF_Q    50176      // QKV [part3][64][34] f32
#define OFF_CONV 76288      // KF 8192 (hi 4096 + lo 4096)
#define OFF_VF   84480      // VF 8192
#define QKV_LD   34
#define FUSED_SMEM 92672
// named barriers
#define BID_FREE 1
#define BID_FULL 2
#define BID_G1   3
#define BID_G2   4

__global__ __launch_bounds__(256, 2)
void fused_kernel(const float* __restrict__ x, const float* __restrict__ scale) {
    extern __shared__ char smc[];
    const uint32_t smb = smem_u32(smc);
    float* QKV = reinterpret_cast<float*>(smc + OFF_Q);   // [part3][64][QKV_LD]

    const int tid = threadIdx.x;
    const int win = blockIdx.x;
    const int w = tid >> 5, lane = tid & 31;
    const int b = win >> 10, wy = (win >> 5) & 31, wx = win & 31;

    // ---- build A hi/lo from x (windowed gather) ----
    for (int idx = tid; idx < 64 * 48; idx += 256) {
        int r = idx / 48, k = (idx - r * 48) * 4;
        int y = (wy << 3) + (r >> 3), xx = (wx << 3) + (r & 7);
        size_t tok = ((size_t)((b << 8) + y)) * IMG + xx;
        float4 v = *reinterpret_cast<const float4*>(&x[tok * CCH + k]);
        uint32_t h01 = pk(bf_hi(v.x), bf_hi(v.y));
        uint32_t h23 = pk(bf_hi(v.z), bf_hi(v.w));
        uint32_t l01 = pk(bf_lo(v.x), bf_lo(v.y));
        uint32_t l23 = pk(bf_lo(v.z), bf_lo(v.w));
        char* rowp = smc + OFF_A + r * A_ROW_B;
        *reinterpret_cast<uint2*>(rowp + 2 * k)       = make_uint2(h01, h23);
        *reinterpret_cast<uint2*>(rowp + 384 + 2 * k) = make_uint2(l01, l23);
    }
    __syncthreads();

    const int qr = lane >> 2;
    const int kq = 2 * (lane & 3);

    if (w < 4) {
        // ================= warps 0-3: GEMM-Q (1 nt, 4 mf) + attention =================
        const int mt = w;
        const int r0 = mt * 16 + qr;
        const uint32_t kfb = smb + OFF_CONV;
        const uint32_t vfb = smb + OFF_VF;

        for (int h = 0; h < 6; h++) {
            float acc[4][4];
            #pragma unroll
            for (int mf = 0; mf < 4; mf++)
                #pragma unroll
                for (int e = 0; e < 4; e++) acc[mf][e] = 0.f;

            #pragma unroll 4
            for (int tg = 0; tg < 12; tg++) {
                const int hf = tg >= 6, s = tg - hf * 6;
                const uint2* bp = reinterpret_cast<const uint2*>(
                    g_wq2 + ((((size_t)(h * 2 + hf) * 12 + w) * 12 + s) * 64) + lane * 2);
                uint2 bh = __ldg(bp);
                uint2 bl = __ldg(bp + 192);
                const uint32_t bhv[2] = { bh.x, bh.y };
                const uint32_t blv[2] = { bl.x, bl.y };
                #pragma unroll
                for (int mf = 0; mf < 4; mf++) {
                    uint32_t ah[4], al[4];
                    uint32_t aaddr = smb + OFF_A + (mf * 16 + (lane & 15)) * A_ROW_B
                                   + (lane >> 4) * 16 + tg * 32;
                    ldsm4(ah, aaddr);
                    ldsm4(al, aaddr + 384);
                    mma16816(acc[mf], ah, bhv);
                    mma16816(acc[mf], al, bhv);
                    mma16816(acc[mf], ah, blv);
                }
            }

            BAR_G128(BID_G1);   // all w0-3 done attention(h-1) Q reads

            {
                int col = w * 8 + kq;
                float b0 = g_bq[h * 96 + col], b1 = g_bq[h * 96 + col + 1];
                #pragma unroll
                for (int mf = 0; mf < 4; mf++) {
                    int row = mf * 16 + qr;
                    float* p0 = &QKV[row * QKV_LD + col];
                    p0[0] = acc[mf][0] + b0;
                    p0[1] = acc[mf][1] + b1;
                    float* p1 = &QKV[(row + 8) * QKV_LD + col];
                    p1[0] = acc[mf][2] + b0;
                    p1[1] = acc[mf][3] + b1;
                }
            }
            BAR_SYNC(BID_FULL);   // waits pack(h) from w4-7; publishes Q writes

            // ---- attention ----
            const float ls = expf(fminf(scale[h], 4.605170185988092f));
            float qv[2][4][2];
            float ss0 = 0.f, ss1 = 0.f;
            #pragma unroll
            for (int ks = 0; ks < 2; ks++)
                #pragma unroll
                for (int reg = 0; reg < 4; reg++) {
                    int r = r0 + ((reg & 1) << 3);
                    int k = ks * 16 + kq + ((reg >> 1) << 3);
                    float2 v = *reinterpret_cast<const float2*>(&QKV[r * QKV_LD + k]);
                    qv[ks][reg][0] = v.x; qv[ks][reg][1] = v.y;
                    float c = fmaf(v.x, v.x, v.y * v.y);
                    if (reg & 1) ss1 += c; else ss0 += c;
                }
            ss0 += __shfl_xor_sync(0xffffffffu, ss0, 1);
            ss0 += __shfl_xor_sync(0xffffffffu, ss0, 2);
            ss1 += __shfl_xor_sync(0xffffffffu, ss1, 1);
            ss1 += __shfl_xor_sync(0xffffffffu, ss1, 2);
            float inv0 = rsqrtf(fmaxf(ss0, 1.55e-05f)) * ls;
            float inv1 = rsqrtf(fmaxf(ss1, 1.55e-05f)) * ls;
            uint32_t qh[2][4], ql[2][4];
            #pragma unroll
            for (int ks = 0; ks < 2; ks++)
                #pragma unroll
                for (int reg = 0; reg < 4; reg++) {
                    float sc = (reg & 1) ? inv1 : inv0;
                    float a = qv[ks][reg][0] * sc, bb = qv[ks][reg][1] * sc;
                    qh[ks][reg] = pk(bf_hi(a), bf_hi(bb));
                    ql[ks][reg] = pk(bf_lo(a), bf_lo(bb));
                }

            float sa[8][4];
            #pragma unroll
            for (int nt = 0; nt < 8; nt++)
                #pragma unroll
                for (int e = 0; e < 4; e++) sa[nt][e] = 0.f;

            #pragma unroll
            for (int ks = 0; ks < 2; ks++)
                #pragma unroll
                for (int nt = 0; nt < 8; nt++) {
                    uint32_t kh[2], kl[2];
                    uint32_t ka = kfb + nt * 512 + ks * 256 + lane * 8;
                    lds64(kh, ka);
                    lds64(kl, ka + 4096);
                    mma16816(sa[nt], qh[ks], kh);
                    mma16816(sa[nt], ql[ks], kh);
                    mma16816(sa[nt], qh[ks], kl);
                }

            float m0 = -1e30f, m1 = -1e30f;
            #pragma unroll
            for (int nt = 0; nt < 8; nt++) {
                const float* rbp = &g_rb[h * 4096 + r0 * 64 + nt * 8 + kq];
                float2 b0 = *reinterpret_cast<const float2*>(rbp);
                float2 b1 = *reinterpret_cast<const float2*>(rbp + 8 * 64);
                sa[nt][0] += b0.x; sa[nt][1] += b0.y;
                sa[nt][2] += b1.x; sa[nt][3] += b1.y;
                m0 = fmaxf(m0, fmaxf(sa[nt][0], sa[nt][1]));
                m1 = fmaxf(m1, fmaxf(sa[nt][2], sa[nt][3]));
            }
            m0 = fmaxf(m0, __shfl_xor_sync(0xffffffffu, m0, 1));
            m0 = fmaxf(m0, __shfl_xor_sync(0xffffffffu, m0, 2));
            m1 = fmaxf(m1, __shfl_xor_sync(0xffffffffu, m1, 1));
            m1 = fmaxf(m1, __shfl_xor_sync(0xffffffffu, m1, 2));

            float s0 = 0.f, s1 = 0.f;
            #pragma unroll
            for (int nt = 0; nt < 8; nt++) {
                sa[nt][0] = __expf(sa[nt][0] - m0); s0 += sa[nt][0];
                sa[nt][1] = __expf(sa[nt][1] - m0); s0 += sa[nt][1];
                sa[nt][2] = __expf(sa[nt][2] - m1); s1 += sa[nt][2];
                sa[nt][3] = __expf(sa[nt][3] - m1); s1 += sa[nt][3];
            }
            s0 += __shfl_xor_sync(0xffffffffu, s0, 1);
            s0 += __shfl_xor_sync(0xffffffffu, s0, 2);
            s1 += __shfl_xor_sync(0xffffffffu, s1, 1);
            s1 += __shfl_xor_sync(0xffffffffu, s1, 2);
            float ri0 = 1.0f / s0, ri1 = 1.0f / s1;

            float o[4][4];
            #pragma unroll
            for (int dt = 0; dt < 4; dt++)
                #pragma unroll
                for (int e = 0; e < 4; e++) o[dt][e] = 0.f;

            #pragma unroll
            for (int kp = 0; kp < 4; kp++) {
                float p0 = sa[2 * kp][0] * ri0,     p1 = sa[2 * kp][1] * ri0;
                float p2 = sa[2 * kp][2] * ri1,     p3 = sa[2 * kp][3] * ri1;
                float p4 = sa[2 * kp + 1][0] * ri0, p5 = sa[2 * kp + 1][1] * ri0;
                float p6 = sa[2 * kp + 1][2] * ri1, p7 = sa[2 * kp + 1][3] * ri1;
                uint32_t ah[4], al[4];
                ah[0] = pk(bf_hi(p0), bf_hi(p1)); al[0] = pk(bf_lo(p0), bf_lo(p1));
                ah[1] = pk(bf_hi(p2), bf_hi(p3)); al[1] = pk(bf_lo(p2), bf_lo(p3));
                ah[2] = pk(bf_hi(p4), bf_hi(p5)); al[2] = pk(bf_lo(p4), bf_lo(p5));
                ah[3] = pk(bf_hi(p6), bf_hi(p7)); al[3] = pk(bf_lo(p6), bf_lo(p7));
                #pragma unroll
                for (int dt = 0; dt < 4; dt++) {
                    uint32_t vh[2], vl[2];
                    uint32_t va = vfb + kp * 1024 + dt * 256 + lane * 8;
                    lds64(vh, va);
                    lds64(vl, va + 4096);
                    mma16816(o[dt], ah, vh);
                    mma16816(o[dt], al, vh);
                    mma16816(o[dt], ah, vl);
                }
            }

            #pragma unroll
            for (int half = 0; half < 2; half++) {
                int r = r0 + half * 8;
                int y = (wy << 3) + (r >> 3), xx = (wx << 3) + (r & 7);
                size_t tok = ((size_t)((b << 8) + y)) * IMG + xx;
                float* op = &g_ao[tok * CCH + h * 32];
                #pragma unroll
                for (int dt = 0; dt < 4; dt++) {
                    float2 st = half ? make_float2(o[dt][2], o[dt][3])
                                     : make_float2(o[dt][0], o[dt][1]);
                    *reinterpret_cast<float2*>(&op[dt * 8 + kq]) = st;
                }
            }
            BAR_ARRIVE(BID_FREE);   // KF/VF free for pack(h+1)
        }
    } else {
        // ================= warps 4-7: GEMM-KV (2 nt, 4 mf) + epilogue + pack =================
        const int idxw = w - 4;
        const int nt0 = 4 + idxw * 2;

        for (int h = 0; h < 6; h++) {
            float acc[4][2][4];
            #pragma unroll
            for (int mf = 0; mf < 4; mf++)
                #pragma unroll
                for (int nf = 0; nf < 2; nf++)
                    #pragma unroll
                    for (int e = 0; e < 4; e++) acc[mf][nf][e] = 0.f;

            #pragma unroll 4
            for (int tg = 0; tg < 12; tg++) {
                const int hf = tg >= 6, s = tg - hf * 6;
                uint2 bh[2], bl[2];
                #pragma unroll
                for (int nf = 0; nf < 2; nf++) {
                    const uint2* bp = reinterpret_cast<const uint2*>(
                        g_wq2 + ((((size_t)(h * 2 + hf) * 12 + nt0 + nf) * 12 + s) * 64) + lane * 2);
                    bh[nf] = __ldg(bp);
                    bl[nf] = __ldg(bp + 192);
                }
                #pragma unroll
                for (int mf = 0; mf < 4; mf++) {
                    uint32_t ah[4], al[4];
                    uint32_t aaddr = smb + OFF_A + (mf * 16 + (lane & 15)) * A_ROW_B
                                   + (lane >> 4) * 16 + tg * 32;
                    ldsm4(ah, aaddr);
                    ldsm4(al, aaddr + 384);
                    #pragma unroll
                    for (int nf = 0; nf < 2; nf++) {
                        const uint32_t bhv[2] = { bh[nf].x, bh[nf].y };
                        const uint32_t blv[2] = { bl[nf].x, bl[nf].y };
                        mma16816(acc[mf][nf], ah, bhv);
                        mma16816(acc[mf][nf], al, bhv);
                        mma16816(acc[mf][nf], ah, blv);
                    }
                }
            }

            BAR_G128(BID_G2);   // all w4-7 done pack(h-1) reads of QKV K/V

            #pragma unroll
            for (int nf = 0; nf < 2; nf++) {
                int colg = (nt0 + nf) * 8 + kq;      // 32..95
                int part = colg >> 5, d = colg & 31;
                float b0 = (part == 2) ? g_bq[h * 96 + colg] : 0.0f;
                float b1 = (part == 2) ? g_bq[h * 96 + colg + 1] : 0.0f;
                #pragma unroll
                for (int mf = 0; mf < 4; mf++) {
                    int row = mf * 16 + qr;
                    float* p0 = &QKV[(part * 64 + row) * QKV_LD + d];
                    p0[0] = acc[mf][nf][0] + b0;
                    p0[1] = acc[mf][nf][1] + b1;
                    float* p1 = &QKV[(part * 64 + row + 8) * QKV_LD + d];
                    p1[0] = acc[mf][nf][2] + b0;
                    p1[1] = acc[mf][nf][3] + b1;
                }
            }
            BAR_G128(BID_G2);   // epilogue visible to pack across w4-7

            if (h > 0) BAR_SYNC(BID_FREE);   // attention(h-1) done with KF/VF

            if (tid < 192) {
                int n = tid - 128;
                const float* kp = &QKV[(1 * 64 + n) * QKV_LD];
                float kv[32];
                float ss = 0.f;
                #pragma unroll
                for (int d = 0; d < 32; d++) { kv[d] = kp[d]; ss = fmaf(kv[d], kv[d], ss); }
                float inv = rsqrtf(fmaxf(ss, 1.55e-05f));
                uint32_t base = OFF_CONV + (n >> 3) * 512 + (n & 7) * 32;
                #pragma unroll
                for (int ks = 0; ks < 2; ks++)
                    #pragma unroll
                    for (int q = 0; q < 4; q++)
                        #pragma unroll
                        for (int reg = 0; reg < 2; reg++) {
                            int k = ks * 16 + 2 * q + 8 * reg;
                            float a = kv[k] * inv, bb = kv[k + 1] * inv;
                            uint32_t addr = base + ks * 256 + q * 8 + reg * 4;
                            *reinterpret_cast<uint32_t*>(smc + addr)        = pk(bf_hi(a), bf_hi(bb));
                            *reinterpret_cast<uint32_t*>(smc + addr + 4096) = pk(bf_lo(a), bf_lo(bb));
                        }
            } else {
                for (int idx = tid - 192; idx < 1024; idx += 64) {
                    int reg = idx & 1, l = (idx >> 1) & 31;
                    int dt = (idx >> 6) & 3, kp2 = (idx >> 8) & 3;
                    int j = kp2 * 16 + 2 * (l & 3) + 8 * reg;
                    int d = dt * 8 + (l >> 2);
                    const float* vp = &QKV[(2 * 64 + j) * QKV_LD + d];
                    float va = vp[0], vb = vp[QKV_LD];
                    uint32_t base = OFF_VF + kp2 * 1024 + dt * 256 + l * 8 + reg * 4;
                    *reinterpret_cast<uint32_t*>(smc + base)        = pk(bf_hi(va), bf_hi(vb));
                    *reinterpret_cast<uint32_t*>(smc + base + 4096) = pk(bf_lo(va), bf_lo(vb));
                }
            }
            BAR_ARRIVE(BID_FULL);   // KF/VF published
        }
    }
}

// ================= proj GEMM — M=64 tiles, full-N warps, 2 CTAs/SM =================
#define P_A_ROW_B 784
#define PROJ_SMEM 50176

__global__ __launch_bounds__(256, 2)
void proj_kernel(float* __restrict__ dst, const float* __restrict__ bias) {
    extern __shared__ char smc[];
    const uint32_t smb = smem_u32(smc);
    const int Ntot = CCH;

    const int tid = threadIdx.x;
    const int m0 = blockIdx.x * 64;
    const int w = tid >> 5, lane = tid & 31;
    const int wm = w >> 2, wn = w & 3;    // wm 0..1 (32 rows), wn 0..3 (6 nt each)

    // ---- build A hi/lo in smem (64 rows) ----
    for (int idx = tid; idx < 64 * 48; idx += 256) {
        int r = idx / 48, k = (idx - r * 48) * 4;
        float4 v = *reinterpret_cast<const float4*>(&g_ao[(size_t)(m0 + r) * CCH + k]);
        uint32_t h01 = pk(bf_hi(v.x), bf_hi(v.y));
        uint32_t h23 = pk(bf_hi(v.z), bf_hi(v.w));
        uint32_t l01 = pk(bf_lo(v.x), bf_lo(v.y));
        uint32_t l23 = pk(bf_lo(v.z), bf_lo(v.w));
        char* rowp = smc + r * P_A_ROW_B;
        *reinterpret_cast<uint2*>(rowp + 2 * k)       = make_uint2(h01, h23);
        *reinterpret_cast<uint2*>(rowp + 384 + 2 * k) = make_uint2(l01, l23);
    }
    __syncthreads();

    const uint32_t a_base = smb + (wm * 32 + (lane & 15)) * P_A_ROW_B + (lane >> 4) * 16;

    float acc[2][6][4];
    #pragma unroll
    for (int i = 0; i < 2; i++)
        #pragma unroll
        for (int j = 0; j < 6; j++)
            #pragma unroll
            for (int e = 0; e < 4; e++) acc[i][j][e] = 0.f;

    #pragma unroll 4
    for (int t = 0; t < 12; t++) {
        uint32_t ah[2][4], al[2][4];
        uint2 bh[6], bl[6];
        #pragma unroll
        for (int nf = 0; nf < 6; nf++) {
            int nt = wn * 6 + nf;
            const uint2* bp = reinterpret_cast<const uint2*>(
                g_wp_frag + (((size_t)nt * 24 + t) * 64 + lane * 2));
            bh[nf] = __ldg(bp);
            bl[nf] = __ldg(bp + 384);           // step +12 (lo)
        }
        #pragma unroll
        for (int mf = 0; mf < 2; mf++) {
            uint32_t aaddr = a_base + mf * 16 * P_A_ROW_B + t * 32;
            ldsm4(ah[mf], aaddr);
            ldsm4(al[mf], aaddr + 384);
        }
        #pragma unroll
        for (int mf = 0; mf < 2; mf++)
            #pragma unroll
            for (int nf = 0; nf < 6; nf++) {
                const uint32_t bhv[2] = { bh[nf].x, bh[nf].y };
                const uint32_t blv[2] = { bl[nf].x, bl[nf].y };
                mma16816(acc[mf][nf], ah[mf], bhv);
                mma16816(acc[mf][nf], al[mf], bhv);
                mma16816(acc[mf][nf], ah[mf], blv);
            }
    }

    #pragma unroll
    for (int mf = 0; mf < 2; mf++) {
        int row = m0 + wm * 32 + mf * 16 + (lane >> 2);
        #pragma unroll
        for (int nf = 0; nf < 6; nf++) {
            int colg = (wn * 6 + nf) * 8 + 2 * (lane & 3);
            float2 bv = *reinterpret_cast<const float2*>(&bias[colg]);
            float2 v0 = make_float2(acc[mf][nf][0] + bv.x, acc[mf][nf][1] + bv.y);
            float2 v1 = make_float2(acc[mf][nf][2] + bv.x, acc[mf][nf][3] + bv.y);
            *reinterpret_cast<float2*>(&dst[(size_t)row * Ntot + colg]) = v0;
            *reinterpret_cast<float2*>(&dst[(size_t)(row + 8) * Ntot + colg]) = v1;
        }
    }
}

// ================= launch =================
extern "C" void kernel_launch(void* const* d_in, const int* in_sizes, int n_in,
                              void* d_out, int out_size) {
    (void)in_sizes; (void)n_in; (void)out_size;
    const float* x      = (const float*)d_in[0];
    const float* qkv_w  = (const float*)d_in[1];
    const float* q_bias = (const float*)d_in[2];
    const float* v_bias = (const float*)d_in[3];
    const float* scale  = (const float*)d_in[4];
    const float* cpb_w1 = (const float*)d_in[5];
    const float* cpb_b1 = (const float*)d_in[6];
    const float* cpb_w2 = (const float*)d_in[7];
    const float* proj_w = (const float*)d_in[8];
    const float* proj_b = (const float*)d_in[9];
    float* out = (float*)d_out;

    cudaFuncSetAttribute(fused_kernel, cudaFuncAttributeMaxDynamicSharedMemorySize, FUSED_SMEM);
    cudaFuncSetAttribute(proj_kernel,  cudaFuncAttributeMaxDynamicSharedMemorySize, PROJ_SMEM);

    prep_kernel<<<64, 256>>>(qkv_w, proj_w, q_bias, v_bias);
    cpb_kernel<<<1, 256>>>(cpb_w1, cpb_b1, cpb_w2);
    fused_kernel<<<NWIN, 256, FUSED_SMEM>>>(x, scale);
    proj_kernel<<<NTOK / 64, 256, PROJ_SMEM>>>(out, proj_b);
}

// round 16
// speedup vs baseline: 1.0381x; 1.0381x over previous
#include <cuda_runtime.h>
#include <cuda_bf16.h>
#include <math.h>
#include <stdint.h>

// ================= problem constants =================
#define IMG    256
#define CCH    192
#define NHEADS 6
#define DTOT   576
#define TOK    64
#define NWIN   4096
#define NTOK   262144

// ================= device scratch =================
__device__ float g_ao [(size_t)NTOK * CCH];             // 201 MB
__device__ uint32_t g_wq2[6 * 2 * 12 * 12 * 64];        // qkv frags [head][half][nt12][s12][64]
__device__ uint32_t g_wp_frag[24 * 24 * 64];            // proj frags [nt24][step24][64]
__device__ float g_bq[DTOT];
__device__ float g_rb[NHEADS * TOK * TOK];

// ================= asm helpers (baseline sm_103 PTX only) =================
__device__ __forceinline__ uint32_t smem_u32(const void* p) {
    uint32_t a;
    asm("{ .reg .u64 t; cvta.to.shared.u64 t, %1; cvt.u32.u64 %0, t; }" : "=r"(a) : "l"(p));
    return a;
}
__device__ __forceinline__ void ldsm4(uint32_t* r, uint32_t addr) {
    asm volatile("ldmatrix.sync.aligned.m8n8.x4.shared.b16 {%0,%1,%2,%3}, [%4];"
                 : "=r"(r[0]), "=r"(r[1]), "=r"(r[2]), "=r"(r[3]) : "r"(addr));
}
__device__ __forceinline__ void lds64(uint32_t* r, uint32_t addr) {
    asm volatile("ld.shared.v2.u32 {%0,%1}, [%2];" : "=r"(r[0]), "=r"(r[1]) : "r"(addr));
}
__device__ __forceinline__ void mma16816(float* d, const uint32_t* a, const uint32_t* b) {
    asm volatile("mma.sync.aligned.m16n8k16.row.col.f32.bf16.bf16.f32 "
                 "{%0,%1,%2,%3}, {%4,%5,%6,%7}, {%8,%9}, {%0,%1,%2,%3};"
                 : "+f"(d[0]), "+f"(d[1]), "+f"(d[2]), "+f"(d[3])
                 : "r"(a[0]), "r"(a[1]), "r"(a[2]), "r"(a[3]), "r"(b[0]), "r"(b[1]));
}
#define BAR_ARRIVE(id) asm volatile("bar.arrive %0, 256;" :: "r"(id) : "memory")
#define BAR_SYNC(id)   asm volatile("bar.sync %0, 256;"   :: "r"(id) : "memory")
#define BAR_G128(id)   asm volatile("bar.sync %0, 128;"   :: "r"(id) : "memory")

__device__ __forceinline__ uint16_t bf_hi(float v) {
    return __bfloat16_as_ushort(__float2bfloat16(v));
}
__device__ __forceinline__ uint16_t bf_lo(float v) {
    __nv_bfloat16 h = __float2bfloat16(v);
    return __bfloat16_as_ushort(__float2bfloat16(v - __bfloat162float(h)));
}
__device__ __forceinline__ uint32_t pk(uint16_t a, uint16_t b) {
    return (uint32_t)a | ((uint32_t)b << 16);
}

// ================= kernel: weight prep =================
__global__ void prep_kernel(const float* __restrict__ qkv_w, const float* __restrict__ proj_w,
                            const float* __restrict__ q_bias, const float* __restrict__ v_bias) {
    int gtid = blockIdx.x * blockDim.x + threadIdx.x;
    int nth = gridDim.x * blockDim.x;
    for (int idx = gtid; idx < 6 * 2 * 12 * 12 * 64; idx += nth) {
        int r = idx & 1, l = (idx >> 1) & 31;
        int blk = idx >> 6;
        int s = blk % 12; blk /= 12;
        int nt = blk % 12; blk /= 12;
        int hf = blk & 1, hd = blk >> 1;
        int k = hf * 96 + (s % 6) * 16 + 2 * (l & 3) + 8 * r;
        int n = hd * 96 + nt * 8 + (l >> 2);
        float v0 = qkv_w[k * DTOT + n];
        float v1 = qkv_w[(k + 1) * DTOT + n];
        uint32_t p0 = (s < 6) ? bf_hi(v0) : bf_lo(v0);
        uint32_t p1 = (s < 6) ? bf_hi(v1) : bf_lo(v1);
        g_wq2[idx] = p0 | (p1 << 16);
    }
    for (int idx = gtid; idx < 24 * 24 * 64; idx += nth) {
        int r = idx & 1, l = (idx >> 1) & 31;
        int st = (idx >> 6) % 24, nt = (idx >> 6) / 24;
        int ko = 16 * (st % 12) + 2 * (l & 3) + 8 * r;
        int n = nt * 8 + (l >> 2);
        float v0 = proj_w[ko * CCH + n];
        float v1 = proj_w[(ko + 1) * CCH + n];
        uint32_t p0 = (st < 12) ? bf_hi(v0) : bf_lo(v0);
        uint32_t p1 = (st < 12) ? bf_hi(v1) : bf_lo(v1);
        g_wp_frag[idx] = p0 | (p1 << 16);
    }
    for (int n = gtid; n < DTOT; n += nth)
        g_bq[n] = (n < 192) ? q_bias[n] : ((n < 384) ? 0.0f : v_bias[n - 384]);
}

// ================= kernel: CPB MLP + gather =================
__global__ void cpb_kernel(const float* __restrict__ w1, const float* __restrict__ b1,
                           const float* __restrict__ w2) {
    __shared__ float tab16[225][6];
    int t = threadIdx.x;
    if (t < 225) {
        float ci = (float)(t / 15 - 7) * (8.0f / 7.0f);
        float cj = (float)(t % 15 - 7) * (8.0f / 7.0f);
        const float inv_log8 = 1.0f / logf(8.0f);
        float tx = copysignf(log1pf(fabsf(ci)) * inv_log8, ci);
        float ty = copysignf(log1pf(fabsf(cj)) * inv_log8, cj);
        float o[6] = {0.f, 0.f, 0.f, 0.f, 0.f, 0.f};
        for (int k = 0; k < 512; k++) {
            float h = fmaxf(tx * w1[k] + ty * w1[512 + k] + b1[k], 0.0f);
            #pragma unroll
            for (int hh = 0; hh < 6; hh++) o[hh] += h * w2[k * 6 + hh];
        }
        #pragma unroll
        for (int hh = 0; hh < 6; hh++) tab16[t][hh] = 16.0f / (1.0f + expf(-o[hh]));
    }
    __syncthreads();
    for (int idx = t; idx < NHEADS * TOK * TOK; idx += blockDim.x) {
        int h = idx >> 12;
        int r = idx & 4095;
        int p = r >> 6, q = r & 63;
        int ri = (p >> 3) - (q >> 3) + 7;
        int rj = (p & 7) - (q & 7) + 7;
        g_rb[idx] = tab16[ri * 15 + rj][h];
    }
}

// ================= fused kernel: column-warp GEMM + double-buffered KF/VF =================
#define A_ROW_B  784
#define OFF_A    0
#define OFF_Q    50176      // QKV [part3][64][34] f32
#define OFF_CONV 76288      // 2 buffers x (KF 8192 + VF 8192)
#define BUF_SZ   16384
#define QKV_LD   34
#define FUSED_SMEM 109056
// named barriers: BOTH handshakes split per buffer parity (deadlock fix —
// producer can lead by 2 heads, so each id carries at most one outstanding wave)
#define BID_G1    3
#define BID_G2    4
#define BID_FREE0 5
#define BID_FREE1 6
#define BID_FULL0 7
#define BID_FULL1 8

__global__ __launch_bounds__(256, 2)
void fused_kernel(const float* __restrict__ x, const float* __restrict__ scale) {
    extern __shared__ char smc[];
    const uint32_t smb = smem_u32(smc);
    float* QKV = reinterpret_cast<float*>(smc + OFF_Q);   // [part3][64][QKV_LD]

    const int tid = threadIdx.x;
    const int win = blockIdx.x;
    const int w = tid >> 5, lane = tid & 31;
    const int b = win >> 10, wy = (win >> 5) & 31, wx = win & 31;

    // ---- build A hi/lo from x (windowed gather) ----
    for (int idx = tid; idx < 64 * 48; idx += 256) {
        int r = idx / 48, k = (idx - r * 48) * 4;
        int y = (wy << 3) + (r >> 3), xx = (wx << 3) + (r & 7);
        size_t tok = ((size_t)((b << 8) + y)) * IMG + xx;
        float4 v = *reinterpret_cast<const float4*>(&x[tok * CCH + k]);
        uint32_t h01 = pk(bf_hi(v.x), bf_hi(v.y));
        uint32_t h23 = pk(bf_hi(v.z), bf_hi(v.w));
        uint32_t l01 = pk(bf_lo(v.x), bf_lo(v.y));
        uint32_t l23 = pk(bf_lo(v.z), bf_lo(v.w));
        char* rowp = smc + OFF_A + r * A_ROW_B;
        *reinterpret_cast<uint2*>(rowp + 2 * k)       = make_uint2(h01, h23);
        *reinterpret_cast<uint2*>(rowp + 384 + 2 * k) = make_uint2(l01, l23);
    }
    __syncthreads();

    const int qr = lane >> 2;
    const int kq = 2 * (lane & 3);

    if (w < 4) {
        // ================= warps 0-3: GEMM-Q (1 nt, 4 mf) + attention =================
        const int mt = w;
        const int r0 = mt * 16 + qr;

        for (int h = 0; h < 6; h++) {
            float acc[4][4];
            #pragma unroll
            for (int mf = 0; mf < 4; mf++)
                #pragma unroll
                for (int e = 0; e < 4; e++) acc[mf][e] = 0.f;

            #pragma unroll 4
            for (int tg = 0; tg < 12; tg++) {
                const int hf = tg >= 6, s = tg - hf * 6;
                const uint2* bp = reinterpret_cast<const uint2*>(
                    g_wq2 + ((((size_t)(h * 2 + hf) * 12 + w) * 12 + s) * 64) + lane * 2);
                uint2 bh = __ldg(bp);
                uint2 bl = __ldg(bp + 192);
                const uint32_t bhv[2] = { bh.x, bh.y };
                const uint32_t blv[2] = { bl.x, bl.y };
                #pragma unroll
                for (int mf = 0; mf < 4; mf++) {
                    uint32_t ah[4], al[4];
                    uint32_t aaddr = smb + OFF_A + (mf * 16 + (lane & 15)) * A_ROW_B
                                   + (lane >> 4) * 16 + tg * 32;
                    ldsm4(ah, aaddr);
                    ldsm4(al, aaddr + 384);
                    mma16816(acc[mf], ah, bhv);
                    mma16816(acc[mf], al, bhv);
                    mma16816(acc[mf], ah, blv);
                }
            }

            BAR_G128(BID_G1);   // all w0-3 done attention(h-1) Q reads

            {
                int col = w * 8 + kq;
                float b0 = g_bq[h * 96 + col], b1 = g_bq[h * 96 + col + 1];
                #pragma unroll
                for (int mf = 0; mf < 4; mf++) {
                    int row = mf * 16 + qr;
                    float* p0 = &QKV[row * QKV_LD + col];
                    p0[0] = acc[mf][0] + b0;
                    p0[1] = acc[mf][1] + b1;
                    float* p1 = &QKV[(row + 8) * QKV_LD + col];
                    p1[0] = acc[mf][2] + b0;
                    p1[1] = acc[mf][3] + b1;
                }
            }
            BAR_SYNC(BID_FULL0 + (h & 1));   // pack(h) done by w4-7; publishes Q writes

            const uint32_t kfb = smb + OFF_CONV + (h & 1) * BUF_SZ;
            const uint32_t vfb = kfb + 8192;

            // ---- attention ----
            const float ls = expf(fminf(scale[h], 4.605170185988092f));
            float qv[2][4][2];
            float ss0 = 0.f, ss1 = 0.f;
            #pragma unroll
            for (int ks = 0; ks < 2; ks++)
                #pragma unroll
                for (int reg = 0; reg < 4; reg++) {
                    int r = r0 + ((reg & 1) << 3);
                    int k = ks * 16 + kq + ((reg >> 1) << 3);
                    float2 v = *reinterpret_cast<const float2*>(&QKV[r * QKV_LD + k]);
                    qv[ks][reg][0] = v.x; qv[ks][reg][1] = v.y;
                    float c = fmaf(v.x, v.x, v.y * v.y);
                    if (reg & 1) ss1 += c; else ss0 += c;
                }
            ss0 += __shfl_xor_sync(0xffffffffu, ss0, 1);
            ss0 += __shfl_xor_sync(0xffffffffu, ss0, 2);
            ss1 += __shfl_xor_sync(0xffffffffu, ss1, 1);
            ss1 += __shfl_xor_sync(0xffffffffu, ss1, 2);
            float inv0 = rsqrtf(fmaxf(ss0, 1.55e-05f)) * ls;
            float inv1 = rsqrtf(fmaxf(ss1, 1.55e-05f)) * ls;
            uint32_t qh[2][4], ql[2][4];
            #pragma unroll
            for (int ks = 0; ks < 2; ks++)
                #pragma unroll
                for (int reg = 0; reg < 4; reg++) {
                    float sc = (reg & 1) ? inv1 : inv0;
                    float a = qv[ks][reg][0] * sc, bb = qv[ks][reg][1] * sc;
                    qh[ks][reg] = pk(bf_hi(a), bf_hi(bb));
                    ql[ks][reg] = pk(bf_lo(a), bf_lo(bb));
                }

            float sa[8][4];
            #pragma unroll
            for (int nt = 0; nt < 8; nt++)
                #pragma unroll
                for (int e = 0; e < 4; e++) sa[nt][e] = 0.f;

            #pragma unroll
            for (int ks = 0; ks < 2; ks++)
                #pragma unroll
                for (int nt = 0; nt < 8; nt++) {
                    uint32_t kh[2], kl[2];
                    uint32_t ka = kfb + nt * 512 + ks * 256 + lane * 8;
                    lds64(kh, ka);
                    lds64(kl, ka + 4096);
                    mma16816(sa[nt], qh[ks], kh);
                    mma16816(sa[nt], ql[ks], kh);
                    mma16816(sa[nt], qh[ks], kl);
                }

            float m0 = -1e30f, m1 = -1e30f;
            #pragma unroll
            for (int nt = 0; nt < 8; nt++) {
                const float* rbp = &g_rb[h * 4096 + r0 * 64 + nt * 8 + kq];
                float2 b0 = *reinterpret_cast<const float2*>(rbp);
                float2 b1 = *reinterpret_cast<const float2*>(rbp + 8 * 64);
                sa[nt][0] += b0.x; sa[nt][1] += b0.y;
                sa[nt][2] += b1.x; sa[nt][3] += b1.y;
                m0 = fmaxf(m0, fmaxf(sa[nt][0], sa[nt][1]));
                m1 = fmaxf(m1, fmaxf(sa[nt][2], sa[nt][3]));
            }
            m0 = fmaxf(m0, __shfl_xor_sync(0xffffffffu, m0, 1));
            m0 = fmaxf(m0, __shfl_xor_sync(0xffffffffu, m0, 2));
            m1 = fmaxf(m1, __shfl_xor_sync(0xffffffffu, m1, 1));
            m1 = fmaxf(m1, __shfl_xor_sync(0xffffffffu, m1, 2));

            float s0 = 0.f, s1 = 0.f;
            #pragma unroll
            for (int nt = 0; nt < 8; nt++) {
                sa[nt][0] = __expf(sa[nt][0] - m0); s0 += sa[nt][0];
                sa[nt][1] = __expf(sa[nt][1] - m0); s0 += sa[nt][1];
                sa[nt][2] = __expf(sa[nt][2] - m1); s1 += sa[nt][2];
                sa[nt][3] = __expf(sa[nt][3] - m1); s1 += sa[nt][3];
            }
            s0 += __shfl_xor_sync(0xffffffffu, s0, 1);
            s0 += __shfl_xor_sync(0xffffffffu, s0, 2);
            s1 += __shfl_xor_sync(0xffffffffu, s1, 1);
            s1 += __shfl_xor_sync(0xffffffffu, s1, 2);
            float ri0 = 1.0f / s0, ri1 = 1.0f / s1;

            float o[4][4];
            #pragma unroll
            for (int dt = 0; dt < 4; dt++)
                #pragma unroll
                for (int e = 0; e < 4; e++) o[dt][e] = 0.f;

            #pragma unroll
            for (int kp = 0; kp < 4; kp++) {
                float p0 = sa[2 * kp][0] * ri0,     p1 = sa[2 * kp][1] * ri0;
                float p2 = sa[2 * kp][2] * ri1,     p3 = sa[2 * kp][3] * ri1;
                float p4 = sa[2 * kp + 1][0] * ri0, p5 = sa[2 * kp + 1][1] * ri0;
                float p6 = sa[2 * kp + 1][2] * ri1, p7 = sa[2 * kp + 1][3] * ri1;
                uint32_t ah[4], al[4];
                ah[0] = pk(bf_hi(p0), bf_hi(p1)); al[0] = pk(bf_lo(p0), bf_lo(p1));
                ah[1] = pk(bf_hi(p2), bf_hi(p3)); al[1] = pk(bf_lo(p2), bf_lo(p3));
                ah[2] = pk(bf_hi(p4), bf_hi(p5)); al[2] = pk(bf_lo(p4), bf_lo(p5));
                ah[3] = pk(bf_hi(p6), bf_hi(p7)); al[3] = pk(bf_lo(p6), bf_lo(p7));
                #pragma unroll
                for (int dt = 0; dt < 4; dt++) {
                    uint32_t vh[2], vl[2];
                    uint32_t va = vfb + kp * 1024 + dt * 256 + lane * 8;
                    lds64(vh, va);
                    lds64(vl, va + 4096);
                    mma16816(o[dt], ah, vh);
                    mma16816(o[dt], al, vh);
                    mma16816(o[dt], ah, vl);
                }
            }

            #pragma unroll
            for (int half = 0; half < 2; half++) {
                int r = r0 + half * 8;
                int y = (wy << 3) + (r >> 3), xx = (wx << 3) + (r & 7);
                size_t tok = ((size_t)((b << 8) + y)) * IMG + xx;
                float* op = &g_ao[tok * CCH + h * 32];
                #pragma unroll
                for (int dt = 0; dt < 4; dt++) {
                    float2 st = half ? make_float2(o[dt][2], o[dt][3])
                                     : make_float2(o[dt][0], o[dt][1]);
                    *reinterpret_cast<float2*>(&op[dt * 8 + kq]) = st;
                }
            }
            if (h <= 3) BAR_ARRIVE(BID_FREE0 + (h & 1));   // buffer h&1 free for pack(h+2)
        }
    } else {
        // ================= warps 4-7: GEMM-KV (2 nt, 4 mf) + epilogue + pack =================
        const int idxw = w - 4;
        const int nt0 = 4 + idxw * 2;

        for (int h = 0; h < 6; h++) {
            float acc[4][2][4];
            #pragma unroll
            for (int mf = 0; mf < 4; mf++)
                #pragma unroll
                for (int nf = 0; nf < 2; nf++)
                    #pragma unroll
                    for (int e = 0; e < 4; e++) acc[mf][nf][e] = 0.f;

            #pragma unroll 4
            for (int tg = 0; tg < 12; tg++) {
                const int hf = tg >= 6, s = tg - hf * 6;
                uint2 bh[2], bl[2];
                #pragma unroll
                for (int nf = 0; nf < 2; nf++) {
                    const uint2* bp = reinterpret_cast<const uint2*>(
                        g_wq2 + ((((size_t)(h * 2 + hf) * 12 + nt0 + nf) * 12 + s) * 64) + lane * 2);
                    bh[nf] = __ldg(bp);
                    bl[nf] = __ldg(bp + 192);
                }
                #pragma unroll
                for (int mf = 0; mf < 4; mf++) {
                    uint32_t ah[4], al[4];
                    uint32_t aaddr = smb + OFF_A + (mf * 16 + (lane & 15)) * A_ROW_B
                                   + (lane >> 4) * 16 + tg * 32;
                    ldsm4(ah, aaddr);
                    ldsm4(al, aaddr + 384);
                    #pragma unroll
                    for (int nf = 0; nf < 2; nf++) {
                        const uint32_t bhv[2] = { bh[nf].x, bh[nf].y };
                        const uint32_t blv[2] = { bl[nf].x, bl[nf].y };
                        mma16816(acc[mf][nf], ah, bhv);
                        mma16816(acc[mf][nf], al, bhv);
                        mma16816(acc[mf][nf], ah, blv);
                    }
                }
            }

            BAR_G128(BID_G2);   // all w4-7 done pack(h-1) reads of QKV K/V

            #pragma unroll
            for (int nf = 0; nf < 2; nf++) {
                int colg = (nt0 + nf) * 8 + kq;      // 32..95
                int part = colg >> 5, d = colg & 31;
                float b0 = (part == 2) ? g_bq[h * 96 + colg] : 0.0f;
                float b1 = (part == 2) ? g_bq[h * 96 + colg + 1] : 0.0f;
                #pragma unroll
                for (int mf = 0; mf < 4; mf++) {
                    int row = mf * 16 + qr;
                    float* p0 = &QKV[(part * 64 + row) * QKV_LD + d];
                    p0[0] = acc[mf][nf][0] + b0;
                    p0[1] = acc[mf][nf][1] + b1;
                    float* p1 = &QKV[(part * 64 + row + 8) * QKV_LD + d];
                    p1[0] = acc[mf][nf][2] + b0;
                    p1[1] = acc[mf][nf][3] + b1;
                }
            }
            BAR_G128(BID_G2);   // epilogue visible to pack across w4-7

            if (h >= 2) BAR_SYNC(BID_FREE0 + (h & 1));   // attention(h-2) done with buffer h&1

            const uint32_t kf_base = OFF_CONV + (h & 1) * BUF_SZ;
            const uint32_t vf_base = kf_base + 8192;

            if (tid < 192) {
                int n = tid - 128;
                const float* kp = &QKV[(1 * 64 + n) * QKV_LD];
                float kv[32];
                float ss = 0.f;
                #pragma unroll
                for (int d = 0; d < 32; d++) { kv[d] = kp[d]; ss = fmaf(kv[d], kv[d], ss); }
                float inv = rsqrtf(fmaxf(ss, 1.55e-05f));
                uint32_t base = kf_base + (n >> 3) * 512 + (n & 7) * 32;
                #pragma unroll
                for (int ks = 0; ks < 2; ks++)
                    #pragma unroll
                    for (int q = 0; q < 4; q++)
                        #pragma unroll
                        for (int reg = 0; reg < 2; reg++) {
                            int k = ks * 16 + 2 * q + 8 * reg;
                            float a = kv[k] * inv, bb = kv[k + 1] * inv;
                            uint32_t addr = base + ks * 256 + q * 8 + reg * 4;
                            *reinterpret_cast<uint32_t*>(smc + addr)        = pk(bf_hi(a), bf_hi(bb));
                            *reinterpret_cast<uint32_t*>(smc + addr + 4096) = pk(bf_lo(a), bf_lo(bb));
                        }
            } else {
                for (int idx = tid - 192; idx < 1024; idx += 64) {
                    int reg = idx & 1, l = (idx >> 1) & 31;
                    int dt = (idx >> 6) & 3, kp2 = (idx >> 8) & 3;
                    int j = kp2 * 16 + 2 * (l & 3) + 8 * reg;
                    int d = dt * 8 + (l >> 2);
                    const float* vp = &QKV[(2 * 64 + j) * QKV_LD + d];
                    float va = vp[0], vb = vp[QKV_LD];
                    uint32_t base = vf_base + kp2 * 1024 + dt * 256 + l * 8 + reg * 4;
                    *reinterpret_cast<uint32_t*>(smc + base)        = pk(bf_hi(va), bf_hi(vb));
                    *reinterpret_cast<uint32_t*>(smc + base + 4096) = pk(bf_lo(va), bf_lo(vb));
                }
            }
            BAR_ARRIVE(BID_FULL0 + (h & 1));   // KF/VF(h) published
        }
    }
}

// ================= proj GEMM — R9 proven: 512 thr, 2 CTAs/SM, B from L2 =================
#define P_A_ROW_B 784
#define P_OFF_A   0
#define PROJ_SMEM 100864

__global__ __launch_bounds__(512, 2)
void proj_kernel(float* __restrict__ dst, const float* __restrict__ bias) {
    extern __shared__ char smc[];
    const uint32_t smb = smem_u32(smc);
    const int Ntot = CCH;

    const int tid = threadIdx.x;
    const int m0 = blockIdx.x * 128;
    const int w = tid >> 5, lane = tid & 31;
    const int wm = w >> 2, wn = w & 3;

    for (int idx = tid; idx < 128 * 48; idx += 512) {
        int r = idx / 48, k = (idx - r * 48) * 4;
        float4 v = *reinterpret_cast<const float4*>(&g_ao[(size_t)(m0 + r) * CCH + k]);
        uint32_t h01 = pk(bf_hi(v.x), bf_hi(v.y));
        uint32_t h23 = pk(bf_hi(v.z), bf_hi(v.w));
        uint32_t l01 = pk(bf_lo(v.x), bf_lo(v.y));
        uint32_t l23 = pk(bf_lo(v.z), bf_lo(v.w));
        char* rowp = smc + P_OFF_A + r * P_A_ROW_B;
        *reinterpret_cast<uint2*>(rowp + 2 * k)       = make_uint2(h01, h23);
        *reinterpret_cast<uint2*>(rowp + 384 + 2 * k) = make_uint2(l01, l23);
    }
    __syncthreads();

    const uint32_t a_base = smb + P_OFF_A + (wm * 32 + (lane & 15)) * P_A_ROW_B + (lane >> 4) * 16;

    for (int c = 0; c < 3; c++) {
        float acc[2][2][4];
        #pragma unroll
        for (int i = 0; i < 2; i++)
            #pragma unroll
            for (int j = 0; j < 2; j++)
                #pragma unroll
                for (int e = 0; e < 4; e++) acc[i][j][e] = 0.f;

        #pragma unroll 4
        for (int t = 0; t < 12; t++) {
            uint32_t ah[2][4], al[2][4];
            uint2 bh[2], bl[2];
            #pragma unroll
            for (int nf = 0; nf < 2; nf++) {
                int nt = c * 8 + wn * 2 + nf;
                const uint2* bp = reinterpret_cast<const uint2*>(
                    g_wp_frag + (((size_t)nt * 24 + t) * 64 + lane * 2));
                bh[nf] = __ldg(bp);
                bl[nf] = __ldg(bp + 384);
            }
            #pragma unroll
            for (int mf = 0; mf < 2; mf++) {
                uint32_t aaddr = a_base + mf * 16 * P_A_ROW_B + t * 32;
                ldsm4(ah[mf], aaddr);
                ldsm4(al[mf], aaddr + 384);
            }
            #pragma unroll
            for (int mf = 0; mf < 2; mf++)
                #pragma unroll
                for (int nf = 0; nf < 2; nf++) {
                    const uint32_t bhv[2] = { bh[nf].x, bh[nf].y };
                    const uint32_t blv[2] = { bl[nf].x, bl[nf].y };
                    mma16816(acc[mf][nf], ah[mf], bhv);
                    mma16816(acc[mf][nf], al[mf], bhv);
                    mma16816(acc[mf][nf], ah[mf], blv);
                }
        }

        #pragma unroll
        for (int mf = 0; mf < 2; mf++) {
            int row = m0 + wm * 32 + mf * 16 + (lane >> 2);
            #pragma unroll
            for (int nf = 0; nf < 2; nf++) {
                int colg = c * 64 + (wn * 2 + nf) * 8 + 2 * (lane & 3);
                float2 bv = *reinterpret_cast<const float2*>(&bias[colg]);
                float2 v0 = make_float2(acc[mf][nf][0] + bv.x, acc[mf][nf][1] + bv.y);
                float2 v1 = make_float2(acc[mf][nf][2] + bv.x, acc[mf][nf][3] + bv.y);
                *reinterpret_cast<float2*>(&dst[(size_t)row * Ntot + colg]) = v0;
                *reinterpret_cast<float2*>(&dst[(size_t)(row + 8) * Ntot + colg]) = v1;
            }
        }
    }
}

// ================= launch =================
extern "C" void kernel_launch(void* const* d_in, const int* in_sizes, int n_in,
                              void* d_out, int out_size) {
    (void)in_sizes; (void)n_in; (void)out_size;
    const float* x      = (const float*)d_in[0];
    const float* qkv_w  = (const float*)d_in[1];
    const float* q_bias = (const float*)d_in[2];
    const float* v_bias = (const float*)d_in[3];
    const float* scale  = (const float*)d_in[4];
    const float* cpb_w1 = (const float*)d_in[5];
    const float* cpb_b1 = (const float*)d_in[6];
    const float* cpb_w2 = (const float*)d_in[7];
    const float* proj_w = (const float*)d_in[8];
    const float* proj_b = (const float*)d_in[9];
    float* out = (float*)d_out;

    cudaFuncSetAttribute(fused_kernel, cudaFuncAttributeMaxDynamicSharedMemorySize, FUSED_SMEM);
    cudaFuncSetAttribute(proj_kernel,  cudaFuncAttributeMaxDynamicSharedMemorySize, PROJ_SMEM);

    prep_kernel<<<64, 256>>>(qkv_w, proj_w, q_bias, v_bias);
    cpb_kernel<<<1, 256>>>(cpb_w1, cpb_b1, cpb_w2);
    fused_kernel<<<NWIN, 256, FUSED_SMEM>>>(x, scale);
    proj_kernel<<<NTOK / 128, 512, PROJ_SMEM>>>(out, proj_b);
}

// round 17
// speedup vs baseline: 1.0449x; 1.0066x over previous
#include <cuda_runtime.h>
#include <cuda_bf16.h>
#include <math.h>
#include <stdint.h>

// ================= problem constants =================
#define IMG    256
#define CCH    192
#define NHEADS 6
#define DTOT   576
#define TOK    64
#define NWIN   4096
#define NTOK   262144

// ================= device scratch =================
__device__ float g_ao [(size_t)NTOK * CCH];             // 201 MB
__device__ uint32_t g_wq2[6 * 2 * 12 * 12 * 64];        // qkv frags [head][half][nt12][s12][64]
__device__ uint32_t g_wp_frag[24 * 24 * 64];            // proj frags [nt24][step24][64]
__device__ float g_bq[DTOT];
__device__ float g_rb[NHEADS * TOK * TOK];

// ================= asm helpers (baseline sm_103 PTX only) =================
__device__ __forceinline__ uint32_t smem_u32(const void* p) {
    uint32_t a;
    asm("{ .reg .u64 t; cvta.to.shared.u64 t, %1; cvt.u32.u64 %0, t; }" : "=r"(a) : "l"(p));
    return a;
}
__device__ __forceinline__ void ldsm4(uint32_t* r, uint32_t addr) {
    asm volatile("ldmatrix.sync.aligned.m8n8.x4.shared.b16 {%0,%1,%2,%3}, [%4];"
                 : "=r"(r[0]), "=r"(r[1]), "=r"(r[2]), "=r"(r[3]) : "r"(addr));
}
__device__ __forceinline__ void lds64(uint32_t* r, uint32_t addr) {
    asm volatile("ld.shared.v2.u32 {%0,%1}, [%2];" : "=r"(r[0]), "=r"(r[1]) : "r"(addr));
}
__device__ __forceinline__ void mma16816(float* d, const uint32_t* a, const uint32_t* b) {
    asm volatile("mma.sync.aligned.m16n8k16.row.col.f32.bf16.bf16.f32 "
                 "{%0,%1,%2,%3}, {%4,%5,%6,%7}, {%8,%9}, {%0,%1,%2,%3};"
                 : "+f"(d[0]), "+f"(d[1]), "+f"(d[2]), "+f"(d[3])
                 : "r"(a[0]), "r"(a[1]), "r"(a[2]), "r"(a[3]), "r"(b[0]), "r"(b[1]));
}
#define BAR_ARRIVE(id) asm volatile("bar.arrive %0, 256;" :: "r"(id) : "memory")
#define BAR_SYNC(id)   asm volatile("bar.sync %0, 256;"   :: "r"(id) : "memory")
#define BAR_G128(id)   asm volatile("bar.sync %0, 128;"   :: "r"(id) : "memory")

__device__ __forceinline__ uint16_t bf_hi(float v) {
    return __bfloat16_as_ushort(__float2bfloat16(v));
}
__device__ __forceinline__ uint16_t bf_lo(float v) {
    __nv_bfloat16 h = __float2bfloat16(v);
    return __bfloat16_as_ushort(__float2bfloat16(v - __bfloat162float(h)));
}
__device__ __forceinline__ uint32_t pk(uint16_t a, uint16_t b) {
    return (uint32_t)a | ((uint32_t)b << 16);
}

// ================= kernel: weight prep =================
__global__ void prep_kernel(const float* __restrict__ qkv_w, const float* __restrict__ proj_w,
                            const float* __restrict__ q_bias, const float* __restrict__ v_bias) {
    int gtid = blockIdx.x * blockDim.x + threadIdx.x;
    int nth = gridDim.x * blockDim.x;
    for (int idx = gtid; idx < 6 * 2 * 12 * 12 * 64; idx += nth) {
        int r = idx & 1, l = (idx >> 1) & 31;
        int blk = idx >> 6;
        int s = blk % 12; blk /= 12;
        int nt = blk % 12; blk /= 12;
        int hf = blk & 1, hd = blk >> 1;
        int k = hf * 96 + (s % 6) * 16 + 2 * (l & 3) + 8 * r;
        int n = hd * 96 + nt * 8 + (l >> 2);
        float v0 = qkv_w[k * DTOT + n];
        float v1 = qkv_w[(k + 1) * DTOT + n];
        uint32_t p0 = (s < 6) ? bf_hi(v0) : bf_lo(v0);
        uint32_t p1 = (s < 6) ? bf_hi(v1) : bf_lo(v1);
        g_wq2[idx] = p0 | (p1 << 16);
    }
    for (int idx = gtid; idx < 24 * 24 * 64; idx += nth) {
        int r = idx & 1, l = (idx >> 1) & 31;
        int st = (idx >> 6) % 24, nt = (idx >> 6) / 24;
        int ko = 16 * (st % 12) + 2 * (l & 3) + 8 * r;
        int n = nt * 8 + (l >> 2);
        float v0 = proj_w[ko * CCH + n];
        float v1 = proj_w[(ko + 1) * CCH + n];
        uint32_t p0 = (st < 12) ? bf_hi(v0) : bf_lo(v0);
        uint32_t p1 = (st < 12) ? bf_hi(v1) : bf_lo(v1);
        g_wp_frag[idx] = p0 | (p1 << 16);
    }
    for (int n = gtid; n < DTOT; n += nth)
        g_bq[n] = (n < 192) ? q_bias[n] : ((n < 384) ? 0.0f : v_bias[n - 384]);
}

// ================= kernel: CPB MLP + gather =================
__global__ void cpb_kernel(const float* __restrict__ w1, const float* __restrict__ b1,
                           const float* __restrict__ w2) {
    __shared__ float tab16[225][6];
    int t = threadIdx.x;
    if (t < 225) {
        float ci = (float)(t / 15 - 7) * (8.0f / 7.0f);
        float cj = (float)(t % 15 - 7) * (8.0f / 7.0f);
        const float inv_log8 = 1.0f / logf(8.0f);
        float tx = copysignf(log1pf(fabsf(ci)) * inv_log8, ci);
        float ty = copysignf(log1pf(fabsf(cj)) * inv_log8, cj);
        float o[6] = {0.f, 0.f, 0.f, 0.f, 0.f, 0.f};
        for (int k = 0; k < 512; k++) {
            float h = fmaxf(tx * w1[k] + ty * w1[512 + k] + b1[k], 0.0f);
            #pragma unroll
            for (int hh = 0; hh < 6; hh++) o[hh] += h * w2[k * 6 + hh];
        }
        #pragma unroll
        for (int hh = 0; hh < 6; hh++) tab16[t][hh] = 16.0f / (1.0f + expf(-o[hh]));
    }
    __syncthreads();
    for (int idx = t; idx < NHEADS * TOK * TOK; idx += blockDim.x) {
        int h = idx >> 12;
        int r = idx & 4095;
        int p = r >> 6, q = r & 63;
        int ri = (p >> 3) - (q >> 3) + 7;
        int rj = (p & 7) - (q & 7) + 7;
        g_rb[idx] = tab16[ri * 15 + rj][h];
    }
}

// ================= fused kernel: R16-passing version (unchanged) =================
#define A_ROW_B  784
#define OFF_A    0
#define OFF_Q    50176
#define OFF_CONV 76288
#define BUF_SZ   16384
#define QKV_LD   34
#define FUSED_SMEM 109056
#define BID_G1    3
#define BID_G2    4
#define BID_FREE0 5
#define BID_FREE1 6
#define BID_FULL0 7
#define BID_FULL1 8

__global__ __launch_bounds__(256, 2)
void fused_kernel(const float* __restrict__ x, const float* __restrict__ scale) {
    extern __shared__ char smc[];
    const uint32_t smb = smem_u32(smc);
    float* QKV = reinterpret_cast<float*>(smc + OFF_Q);

    const int tid = threadIdx.x;
    const int win = blockIdx.x;
    const int w = tid >> 5, lane = tid & 31;
    const int b = win >> 10, wy = (win >> 5) & 31, wx = win & 31;

    for (int idx = tid; idx < 64 * 48; idx += 256) {
        int r = idx / 48, k = (idx - r * 48) * 4;
        int y = (wy << 3) + (r >> 3), xx = (wx << 3) + (r & 7);
        size_t tok = ((size_t)((b << 8) + y)) * IMG + xx;
        float4 v = *reinterpret_cast<const float4*>(&x[tok * CCH + k]);
        uint32_t h01 = pk(bf_hi(v.x), bf_hi(v.y));
        uint32_t h23 = pk(bf_hi(v.z), bf_hi(v.w));
        uint32_t l01 = pk(bf_lo(v.x), bf_lo(v.y));
        uint32_t l23 = pk(bf_lo(v.z), bf_lo(v.w));
        char* rowp = smc + OFF_A + r * A_ROW_B;
        *reinterpret_cast<uint2*>(rowp + 2 * k)       = make_uint2(h01, h23);
        *reinterpret_cast<uint2*>(rowp + 384 + 2 * k) = make_uint2(l01, l23);
    }
    __syncthreads();

    const int qr = lane >> 2;
    const int kq = 2 * (lane & 3);

    if (w < 4) {
        const int mt = w;
        const int r0 = mt * 16 + qr;

        for (int h = 0; h < 6; h++) {
            float acc[4][4];
            #pragma unroll
            for (int mf = 0; mf < 4; mf++)
                #pragma unroll
                for (int e = 0; e < 4; e++) acc[mf][e] = 0.f;

            #pragma unroll 4
            for (int tg = 0; tg < 12; tg++) {
                const int hf = tg >= 6, s = tg - hf * 6;
                const uint2* bp = reinterpret_cast<const uint2*>(
                    g_wq2 + ((((size_t)(h * 2 + hf) * 12 + w) * 12 + s) * 64) + lane * 2);
                uint2 bh = __ldg(bp);
                uint2 bl = __ldg(bp + 192);
                const uint32_t bhv[2] = { bh.x, bh.y };
                const uint32_t blv[2] = { bl.x, bl.y };
                #pragma unroll
                for (int mf = 0; mf < 4; mf++) {
                    uint32_t ah[4], al[4];
                    uint32_t aaddr = smb + OFF_A + (mf * 16 + (lane & 15)) * A_ROW_B
                                   + (lane >> 4) * 16 + tg * 32;
                    ldsm4(ah, aaddr);
                    ldsm4(al, aaddr + 384);
                    mma16816(acc[mf], ah, bhv);
                    mma16816(acc[mf], al, bhv);
                    mma16816(acc[mf], ah, blv);
                }
            }

            BAR_G128(BID_G1);

            {
                int col = w * 8 + kq;
                float b0 = g_bq[h * 96 + col], b1 = g_bq[h * 96 + col + 1];
                #pragma unroll
                for (int mf = 0; mf < 4; mf++) {
                    int row = mf * 16 + qr;
                    float* p0 = &QKV[row * QKV_LD + col];
                    p0[0] = acc[mf][0] + b0;
                    p0[1] = acc[mf][1] + b1;
                    float* p1 = &QKV[(row + 8) * QKV_LD + col];
                    p1[0] = acc[mf][2] + b0;
                    p1[1] = acc[mf][3] + b1;
                }
            }
            BAR_SYNC(BID_FULL0 + (h & 1));

            const uint32_t kfb = smb + OFF_CONV + (h & 1) * BUF_SZ;
            const uint32_t vfb = kfb + 8192;

            const float ls = expf(fminf(scale[h], 4.605170185988092f));
            float qv[2][4][2];
            float ss0 = 0.f, ss1 = 0.f;
            #pragma unroll
            for (int ks = 0; ks < 2; ks++)
                #pragma unroll
                for (int reg = 0; reg < 4; reg++) {
                    int r = r0 + ((reg & 1) << 3);
                    int k = ks * 16 + kq + ((reg >> 1) << 3);
                    float2 v = *reinterpret_cast<const float2*>(&QKV[r * QKV_LD + k]);
                    qv[ks][reg][0] = v.x; qv[ks][reg][1] = v.y;
                    float c = fmaf(v.x, v.x, v.y * v.y);
                    if (reg & 1) ss1 += c; else ss0 += c;
                }
            ss0 += __shfl_xor_sync(0xffffffffu, ss0, 1);
            ss0 += __shfl_xor_sync(0xffffffffu, ss0, 2);
            ss1 += __shfl_xor_sync(0xffffffffu, ss1, 1);
            ss1 += __shfl_xor_sync(0xffffffffu, ss1, 2);
            float inv0 = rsqrtf(fmaxf(ss0, 1.55e-05f)) * ls;
            float inv1 = rsqrtf(fmaxf(ss1, 1.55e-05f)) * ls;
            uint32_t qh[2][4], ql[2][4];
            #pragma unroll
            for (int ks = 0; ks < 2; ks++)
                #pragma unroll
                for (int reg = 0; reg < 4; reg++) {
                    float sc = (reg & 1) ? inv1 : inv0;
                    float a = qv[ks][reg][0] * sc, bb = qv[ks][reg][1] * sc;
                    qh[ks][reg] = pk(bf_hi(a), bf_hi(bb));
                    ql[ks][reg] = pk(bf_lo(a), bf_lo(bb));
                }

            float sa[8][4];
            #pragma unroll
            for (int nt = 0; nt < 8; nt++)
                #pragma unroll
                for (int e = 0; e < 4; e++) sa[nt][e] = 0.f;

            #pragma unroll
            for (int ks = 0; ks < 2; ks++)
                #pragma unroll
                for (int nt = 0; nt < 8; nt++) {
                    uint32_t kh[2], kl[2];
                    uint32_t ka = kfb + nt * 512 + ks * 256 + lane * 8;
                    lds64(kh, ka);
                    lds64(kl, ka + 4096);
                    mma16816(sa[nt], qh[ks], kh);
                    mma16816(sa[nt], ql[ks], kh);
                    mma16816(sa[nt], qh[ks], kl);
                }

            float m0 = -1e30f, m1 = -1e30f;
            #pragma unroll
            for (int nt = 0; nt < 8; nt++) {
                const float* rbp = &g_rb[h * 4096 + r0 * 64 + nt * 8 + kq];
                float2 b0 = *reinterpret_cast<const float2*>(rbp);
                float2 b1 = *reinterpret_cast<const float2*>(rbp + 8 * 64);
                sa[nt][0] += b0.x; sa[nt][1] += b0.y;
                sa[nt][2] += b1.x; sa[nt][3] += b1.y;
                m0 = fmaxf(m0, fmaxf(sa[nt][0], sa[nt][1]));
                m1 = fmaxf(m1, fmaxf(sa[nt][2], sa[nt][3]));
            }
            m0 = fmaxf(m0, __shfl_xor_sync(0xffffffffu, m0, 1));
            m0 = fmaxf(m0, __shfl_xor_sync(0xffffffffu, m0, 2));
            m1 = fmaxf(m1, __shfl_xor_sync(0xffffffffu, m1, 1));
            m1 = fmaxf(m1, __shfl_xor_sync(0xffffffffu, m1, 2));

            float s0 = 0.f, s1 = 0.f;
            #pragma unroll
            for (int nt = 0; nt < 8; nt++) {
                sa[nt][0] = __expf(sa[nt][0] - m0); s0 += sa[nt][0];
                sa[nt][1] = __expf(sa[nt][1] - m0); s0 += sa[nt][1];
                sa[nt][2] = __expf(sa[nt][2] - m1); s1 += sa[nt][2];
                sa[nt][3] = __expf(sa[nt][3] - m1); s1 += sa[nt][3];
            }
            s0 += __shfl_xor_sync(0xffffffffu, s0, 1);
            s0 += __shfl_xor_sync(0xffffffffu, s0, 2);
            s1 += __shfl_xor_sync(0xffffffffu, s1, 1);
            s1 += __shfl_xor_sync(0xffffffffu, s1, 2);
            float ri0 = 1.0f / s0, ri1 = 1.0f / s1;

            float o[4][4];
            #pragma unroll
            for (int dt = 0; dt < 4; dt++)
                #pragma unroll
                for (int e = 0; e < 4; e++) o[dt][e] = 0.f;

            #pragma unroll
            for (int kp = 0; kp < 4; kp++) {
                float p0 = sa[2 * kp][0] * ri0,     p1 = sa[2 * kp][1] * ri0;
                float p2 = sa[2 * kp][2] * ri1,     p3 = sa[2 * kp][3] * ri1;
                float p4 = sa[2 * kp + 1][0] * ri0, p5 = sa[2 * kp + 1][1] * ri0;
                float p6 = sa[2 * kp + 1][2] * ri1, p7 = sa[2 * kp + 1][3] * ri1;
                uint32_t ah[4], al[4];
                ah[0] = pk(bf_hi(p0), bf_hi(p1)); al[0] = pk(bf_lo(p0), bf_lo(p1));
                ah[1] = pk(bf_hi(p2), bf_hi(p3)); al[1] = pk(bf_lo(p2), bf_lo(p3));
                ah[2] = pk(bf_hi(p4), bf_hi(p5)); al[2] = pk(bf_lo(p4), bf_lo(p5));
                ah[3] = pk(bf_hi(p6), bf_hi(p7)); al[3] = pk(bf_lo(p6), bf_lo(p7));
                #pragma unroll
                for (int dt = 0; dt < 4; dt++) {
                    uint32_t vh[2], vl[2];
                    uint32_t va = vfb + kp * 1024 + dt * 256 + lane * 8;
                    lds64(vh, va);
                    lds64(vl, va + 4096);
                    mma16816(o[dt], ah, vh);
                    mma16816(o[dt], al, vh);
                    mma16816(o[dt], ah, vl);
                }
            }

            #pragma unroll
            for (int half = 0; half < 2; half++) {
                int r = r0 + half * 8;
                int y = (wy << 3) + (r >> 3), xx = (wx << 3) + (r & 7);
                size_t tok = ((size_t)((b << 8) + y)) * IMG + xx;
                float* op = &g_ao[tok * CCH + h * 32];
                #pragma unroll
                for (int dt = 0; dt < 4; dt++) {
                    float2 st = half ? make_float2(o[dt][2], o[dt][3])
                                     : make_float2(o[dt][0], o[dt][1]);
                    *reinterpret_cast<float2*>(&op[dt * 8 + kq]) = st;
                }
            }
            if (h <= 3) BAR_ARRIVE(BID_FREE0 + (h & 1));
        }
    } else {
        const int idxw = w - 4;
        const int nt0 = 4 + idxw * 2;

        for (int h = 0; h < 6; h++) {
            float acc[4][2][4];
            #pragma unroll
            for (int mf = 0; mf < 4; mf++)
                #pragma unroll
                for (int nf = 0; nf < 2; nf++)
                    #pragma unroll
                    for (int e = 0; e < 4; e++) acc[mf][nf][e] = 0.f;

            #pragma unroll 4
            for (int tg = 0; tg < 12; tg++) {
                const int hf = tg >= 6, s = tg - hf * 6;
                uint2 bh[2], bl[2];
                #pragma unroll
                for (int nf = 0; nf < 2; nf++) {
                    const uint2* bp = reinterpret_cast<const uint2*>(
                        g_wq2 + ((((size_t)(h * 2 + hf) * 12 + nt0 + nf) * 12 + s) * 64) + lane * 2);
                    bh[nf] = __ldg(bp);
                    bl[nf] = __ldg(bp + 192);
                }
                #pragma unroll
                for (int mf = 0; mf < 4; mf++) {
                    uint32_t ah[4], al[4];
                    uint32_t aaddr = smb + OFF_A + (mf * 16 + (lane & 15)) * A_ROW_B
                                   + (lane >> 4) * 16 + tg * 32;
                    ldsm4(ah, aaddr);
                    ldsm4(al, aaddr + 384);
                    #pragma unroll
                    for (int nf = 0; nf < 2; nf++) {
                        const uint32_t bhv[2] = { bh[nf].x, bh[nf].y };
                        const uint32_t blv[2] = { bl[nf].x, bl[nf].y };
                        mma16816(acc[mf][nf], ah, bhv);
                        mma16816(acc[mf][nf], al, bhv);
                        mma16816(acc[mf][nf], ah, blv);
                    }
                }
            }

            BAR_G128(BID_G2);

            #pragma unroll
            for (int nf = 0; nf < 2; nf++) {
                int colg = (nt0 + nf) * 8 + kq;
                int part = colg >> 5, d = colg & 31;
                float b0 = (part == 2) ? g_bq[h * 96 + colg] : 0.0f;
                float b1 = (part == 2) ? g_bq[h * 96 + colg + 1] : 0.0f;
                #pragma unroll
                for (int mf = 0; mf < 4; mf++) {
                    int row = mf * 16 + qr;
                    float* p0 = &QKV[(part * 64 + row) * QKV_LD + d];
                    p0[0] = acc[mf][nf][0] + b0;
                    p0[1] = acc[mf][nf][1] + b1;
                    float* p1 = &QKV[(part * 64 + row + 8) * QKV_LD + d];
                    p1[0] = acc[mf][nf][2] + b0;
                    p1[1] = acc[mf][nf][3] + b1;
                }
            }
            BAR_G128(BID_G2);

            if (h >= 2) BAR_SYNC(BID_FREE0 + (h & 1));

            const uint32_t kf_base = OFF_CONV + (h & 1) * BUF_SZ;
            const uint32_t vf_base = kf_base + 8192;

            if (tid < 192) {
                int n = tid - 128;
                const float* kp = &QKV[(1 * 64 + n) * QKV_LD];
                float kv[32];
                float ss = 0.f;
                #pragma unroll
                for (int d = 0; d < 32; d++) { kv[d] = kp[d]; ss = fmaf(kv[d], kv[d], ss); }
                float inv = rsqrtf(fmaxf(ss, 1.55e-05f));
                uint32_t base = kf_base + (n >> 3) * 512 + (n & 7) * 32;
                #pragma unroll
                for (int ks = 0; ks < 2; ks++)
                    #pragma unroll
                    for (int q = 0; q < 4; q++)
                        #pragma unroll
                        for (int reg = 0; reg < 2; reg++) {
                            int k = ks * 16 + 2 * q + 8 * reg;
                            float a = kv[k] * inv, bb = kv[k + 1] * inv;
                            uint32_t addr = base + ks * 256 + q * 8 + reg * 4;
                            *reinterpret_cast<uint32_t*>(smc + addr)        = pk(bf_hi(a), bf_hi(bb));
                            *reinterpret_cast<uint32_t*>(smc + addr + 4096) = pk(bf_lo(a), bf_lo(bb));
                        }
            } else {
                for (int idx = tid - 192; idx < 1024; idx += 64) {
                    int reg = idx & 1, l = (idx >> 1) & 31;
                    int dt = (idx >> 6) & 3, kp2 = (idx >> 8) & 3;
                    int j = kp2 * 16 + 2 * (l & 3) + 8 * reg;
                    int d = dt * 8 + (l >> 2);
                    const float* vp = &QKV[(2 * 64 + j) * QKV_LD + d];
                    float va = vp[0], vb = vp[QKV_LD];
                    uint32_t base = vf_base + kp2 * 1024 + dt * 256 + l * 8 + reg * 4;
                    *reinterpret_cast<uint32_t*>(smc + base)        = pk(bf_hi(va), bf_hi(vb));
                    *reinterpret_cast<uint32_t*>(smc + base + 4096) = pk(bf_lo(va), bf_lo(vb));
                }
            }
            BAR_ARRIVE(BID_FULL0 + (h & 1));
        }
    }
}

// ================= proj GEMM — M=64, t-outer, A-frags loaded once, 384 thr x 2 CTAs =================
#define P_A_ROW_B 784
#define PROJ_SMEM 50176

__global__ __launch_bounds__(384, 2)
void proj_kernel(float* __restrict__ dst, const float* __restrict__ bias) {
    extern __shared__ char smc[];
    const uint32_t smb = smem_u32(smc);
    const int Ntot = CCH;

    const int tid = threadIdx.x;
    const int m0 = blockIdx.x * 64;
    const int w = tid >> 5, lane = tid & 31;
    const int wm = w / 6, wn = w % 6;     // wm 0..1 (32 rows each), wn 0..5 (4 nt each)

    // ---- build A hi/lo in smem (64 rows) ----
    for (int idx = tid; idx < 64 * 48; idx += 384) {
        int r = idx / 48, k = (idx - r * 48) * 4;
        float4 v = *reinterpret_cast<const float4*>(&g_ao[(size_t)(m0 + r) * CCH + k]);
        uint32_t h01 = pk(bf_hi(v.x), bf_hi(v.y));
        uint32_t h23 = pk(bf_hi(v.z), bf_hi(v.w));
        uint32_t l01 = pk(bf_lo(v.x), bf_lo(v.y));
        uint32_t l23 = pk(bf_lo(v.z), bf_lo(v.w));
        char* rowp = smc + r * P_A_ROW_B;
        *reinterpret_cast<uint2*>(rowp + 2 * k)       = make_uint2(h01, h23);
        *reinterpret_cast<uint2*>(rowp + 384 + 2 * k) = make_uint2(l01, l23);
    }
    __syncthreads();

    const uint32_t a_base = smb + (wm * 32 + (lane & 15)) * P_A_ROW_B + (lane >> 4) * 16;

    float acc[2][4][4];
    #pragma unroll
    for (int i = 0; i < 2; i++)
        #pragma unroll
        for (int j = 0; j < 4; j++)
            #pragma unroll
            for (int e = 0; e < 4; e++) acc[i][j][e] = 0.f;

    #pragma unroll 4
    for (int t = 0; t < 12; t++) {
        uint32_t ah[2][4], al[2][4];
        uint2 bh[4], bl[4];
        #pragma unroll
        for (int nf = 0; nf < 4; nf++) {
            int nt = wn * 4 + nf;
            const uint2* bp = reinterpret_cast<const uint2*>(
                g_wp_frag + (((size_t)nt * 24 + t) * 64 + lane * 2));
            bh[nf] = __ldg(bp);
            bl[nf] = __ldg(bp + 384);           // step +12 (lo)
        }
        #pragma unroll
        for (int mf = 0; mf < 2; mf++) {
            uint32_t aaddr = a_base + mf * 16 * P_A_ROW_B + t * 32;
            ldsm4(ah[mf], aaddr);
            ldsm4(al[mf], aaddr + 384);
        }
        #pragma unroll
        for (int mf = 0; mf < 2; mf++)
            #pragma unroll
            for (int nf = 0; nf < 4; nf++) {
                const uint32_t bhv[2] = { bh[nf].x, bh[nf].y };
                const uint32_t blv[2] = { bl[nf].x, bl[nf].y };
                mma16816(acc[mf][nf], ah[mf], bhv);
                mma16816(acc[mf][nf], al[mf], bhv);
                mma16816(acc[mf][nf], ah[mf], blv);
            }
    }

    #pragma unroll
    for (int mf = 0; mf < 2; mf++) {
        int row = m0 + wm * 32 + mf * 16 + (lane >> 2);
        #pragma unroll
        for (int nf = 0; nf < 4; nf++) {
            int colg = (wn * 4 + nf) * 8 + 2 * (lane & 3);
            float2 bv = *reinterpret_cast<const float2*>(&bias[colg]);
            float2 v0 = make_float2(acc[mf][nf][0] + bv.x, acc[mf][nf][1] + bv.y);
            float2 v1 = make_float2(acc[mf][nf][2] + bv.x, acc[mf][nf][3] + bv.y);
            *reinterpret_cast<float2*>(&dst[(size_t)row * Ntot + colg]) = v0;
            *reinterpret_cast<float2*>(&dst[(size_t)(row + 8) * Ntot + colg]) = v1;
        }
    }
}

// ================= launch =================
extern "C" void kernel_launch(void* const* d_in, const int* in_sizes, int n_in,
                              void* d_out, int out_size) {
    (void)in_sizes; (void)n_in; (void)out_size;
    const float* x      = (const float*)d_in[0];
    const float* qkv_w  = (const float*)d_in[1];
    const float* q_bias = (const float*)d_in[2];
    const float* v_bias = (const float*)d_in[3];
    const float* scale  = (const float*)d_in[4];
    const float* cpb_w1 = (const float*)d_in[5];
    const float* cpb_b1 = (const float*)d_in[6];
    const float* cpb_w2 = (const float*)d_in[7];
    const float* proj_w = (const float*)d_in[8];
    const float* proj_b = (const float*)d_in[9];
    float* out = (float*)d_out;

    cudaFuncSetAttribute(fused_kernel, cudaFuncAttributeMaxDynamicSharedMemorySize, FUSED_SMEM);
    cudaFuncSetAttribute(proj_kernel,  cudaFuncAttributeMaxDynamicSharedMemorySize, PROJ_SMEM);

    prep_kernel<<<64, 256>>>(qkv_w, proj_w, q_bias, v_bias);
    cpb_kernel<<<1, 256>>>(cpb_w1, cpb_b1, cpb_w2);
    fused_kernel<<<NWIN, 256, FUSED_SMEM>>>(x, scale);
    proj_kernel<<<NTOK / 64, 384, PROJ_SMEM>>>(out, proj_b);
}